// round 1
// baseline (speedup 1.0000x reference)
#include <cuda_runtime.h>

// PoseNoiseTransform: per-column quaternion scan.
//   q_dot[t] = (q[t+1] * conj(q[t])) * normalize((noise[t]-0.5)*[1,.05,.05,.05])
//   out[0]   = q[0];  out[t+1] = q_dot[t] * out[t]
// Shapes fixed by the dataset: ts=2048, ns=4096.
//
// Layout convention: float4 (x,y,z,w) fields hold quaternion (w,x,y,z).

#define TS     2048
#define NS     4096
#define STEPS  (TS - 1)          // 2047 scan steps
#define COLS   32                // columns per block (warp-coalesced)
#define SLOTS  16                // time-slots per block
#define CSTEP  4                 // steps per thread per tile
#define TILE   (SLOTS * CSTEP)   // 64 steps per tile
#define NTILES ((STEPS + TILE - 1) / TILE)   // 32

__device__ __forceinline__ float4 qmul4(float4 a, float4 b) {
    float4 r;
    r.x = a.x*b.x - a.y*b.y - a.z*b.z - a.w*b.w;   // w
    r.y = a.x*b.y + a.y*b.x + a.z*b.w - a.w*b.z;   // x
    r.z = a.x*b.z - a.y*b.w + a.z*b.x + a.w*b.y;   // y
    r.w = a.x*b.w + a.y*b.z - a.z*b.y + a.w*b.x;   // z
    return r;
}

// a * conj(b)
__device__ __forceinline__ float4 qmul_conj4(float4 a, float4 b) {
    float4 r;
    r.x =  a.x*b.x + a.y*b.y + a.z*b.z + a.w*b.w;
    r.y = -a.x*b.y + a.y*b.x - a.z*b.w + a.w*b.z;
    r.z = -a.x*b.z + a.y*b.w + a.z*b.x - a.w*b.y;
    r.w = -a.x*b.w - a.y*b.z + a.z*b.y + a.w*b.x;
    return r;
}

__global__ __launch_bounds__(COLS * SLOTS, 1)
void pose_scan_kernel(const float4* __restrict__ q,
                      const float4* __restrict__ noise,
                      float4* __restrict__ out)
{
    __shared__ float4 s_agg [SLOTS][COLS];   // per-slot inclusive chunk product
    __shared__ float4 s_excl[SLOTS][COLS];   // per-slot exclusive prefix (incl. carry & q0)
    __shared__ float4 s_carry[COLS];         // running state across tiles (= last q_out)

    const int tx   = threadIdx.x;
    const int col  = tx & (COLS - 1);
    const int slot = tx / COLS;              // warp id: one warp == one slot, 32 cols
    const int n    = blockIdx.x * COLS + col;

    // Seed carry with q[0]; emit output row 0. (warp 0 writes, warp 0 reads -> no sync needed
    // before the first scan; the first __syncthreads in the loop orders it for everyone else.)
    if (slot == 0) {
        float4 q0 = q[n];
        s_carry[col] = q0;
        out[n] = q0;
    }

    float4 qb[CSTEP + 1];
    float4 nb[CSTEP];

    // Prime loads for tile 0.
    {
        const int t0 = slot * CSTEP;
        #pragma unroll
        for (int i = 0; i <= CSTEP; i++) qb[i] = q[min(t0 + i, TS - 1) * NS + n];
        #pragma unroll
        for (int i = 0; i < CSTEP; i++)  nb[i] = noise[min(t0 + i, STEPS - 1) * NS + n];
    }

    float4 L[CSTEP];   // local inclusive chain (newest factor on the left)

    for (int tile = 0; tile < NTILES; tile++) {
        const int t0 = tile * TILE + slot * CSTEP;

        // ---- phase 1: local chain over CSTEP steps (registers only) ----
        float4 acc = make_float4(1.f, 0.f, 0.f, 0.f);
        #pragma unroll
        for (int i = 0; i < CSTEP; i++) {
            float4 qd = qmul_conj4(qb[i + 1], qb[i]);          // q[t+1] * conj(q[t])
            float vw =  nb[i].x - 0.5f;
            float vx = (nb[i].y - 0.5f) * 0.05f;
            float vy = (nb[i].z - 0.5f) * 0.05f;
            float vz = (nb[i].w - 0.5f) * 0.05f;
            float rn = rsqrtf(vw*vw + vx*vx + vy*vy + vz*vz);
            float4 qs = make_float4(vw*rn, vx*rn, vy*rn, vz*rn);
            float4 qd2 = qmul4(qd, qs);
            if (t0 + i >= STEPS) qd2 = make_float4(1.f, 0.f, 0.f, 0.f);  // pad identity
            acc = (i == 0) ? qd2 : qmul4(qd2, acc);
            L[i] = acc;
        }
        s_agg[slot][col] = acc;

        // ---- prefetch next tile BEFORE the sync so LDGs fly under the scan ----
        if (tile + 1 < NTILES) {
            const int t1 = (tile + 1) * TILE + slot * CSTEP;
            #pragma unroll
            for (int i = 0; i <= CSTEP; i++) qb[i] = q[min(t1 + i, TS - 1) * NS + n];
            #pragma unroll
            for (int i = 0; i < CSTEP; i++)  nb[i] = noise[min(t1 + i, STEPS - 1) * NS + n];
        }

        __syncthreads();

        // ---- phase 2: warp 0 serially scans the 16 slot aggregates per column ----
        if (slot == 0) {
            float4 E = s_carry[col];
            #pragma unroll
            for (int s = 0; s < SLOTS; s++) {
                s_excl[s][col] = E;
                E = qmul4(s_agg[s][col], E);
            }
            s_carry[col] = E;
        }
        __syncthreads();

        // ---- phase 3: apply exclusive prefix, write outputs (coalesced STG.128) ----
        float4 E = s_excl[slot][col];
        #pragma unroll
        for (int i = 0; i < CSTEP; i++) {
            int t = t0 + i;
            if (t < STEPS) out[(t + 1) * NS + n] = qmul4(L[i], E);
        }
    }
}

extern "C" void kernel_launch(void* const* d_in, const int* in_sizes, int n_in,
                              void* d_out, int out_size)
{
    const float4* q     = (const float4*)d_in[0];   // [2048, 4096, 4] f32
    const float4* noise = (const float4*)d_in[1];   // [2047, 4096, 4] f32
    float4* out         = (float4*)d_out;           // [2048, 4096, 4] f32

    pose_scan_kernel<<<NS / COLS, COLS * SLOTS>>>(q, noise, out);
}

// round 2
// speedup vs baseline: 1.0299x; 1.0299x over previous
#include <cuda_runtime.h>

// PoseNoiseTransform: per-column quaternion scan.
//   q_dot[t] = (q[t+1] * conj(q[t])) * normalize((noise[t]-0.5)*[1,.05,.05,.05])
//   out[0]   = q[0];  out[t+1] = q_dot[t] * out[t]
// ts=2048, ns=4096 fixed.
//
// float4 (x,y,z,w) fields hold quaternion (w,x,y,z).

#define TS     2048
#define NS     4096
#define STEPS  (TS - 1)          // 2047 scan steps
#define COLS   16                // columns per block
#define SLOTS  16                // time-slots per block
#define CSTEP  4                 // steps per thread per tile
#define TILE   (SLOTS * CSTEP)   // 64 steps per tile
#define NTILES ((STEPS + TILE - 1) / TILE)   // 32
#define NTHREADS (COLS * SLOTS)  // 256

__device__ __forceinline__ float4 qmul4(float4 a, float4 b) {
    float4 r;
    r.x = a.x*b.x - a.y*b.y - a.z*b.z - a.w*b.w;   // w
    r.y = a.x*b.y + a.y*b.x + a.z*b.w - a.w*b.z;   // x
    r.z = a.x*b.z - a.y*b.w + a.z*b.x + a.w*b.y;   // y
    r.w = a.x*b.w + a.y*b.z - a.z*b.y + a.w*b.x;   // z
    return r;
}

// a * conj(b)
__device__ __forceinline__ float4 qmul_conj4(float4 a, float4 b) {
    float4 r;
    r.x =  a.x*b.x + a.y*b.y + a.z*b.z + a.w*b.w;
    r.y = -a.x*b.y + a.y*b.x - a.z*b.w + a.w*b.z;
    r.z = -a.x*b.z + a.y*b.w + a.z*b.x - a.w*b.y;
    r.w = -a.x*b.w - a.y*b.z + a.z*b.y + a.w*b.x;
    return r;
}

__device__ __forceinline__ float4 shfl_up4(float4 v, int delta) {
    float4 r;
    r.x = __shfl_up_sync(0xffffffffu, v.x, delta, 16);
    r.y = __shfl_up_sync(0xffffffffu, v.y, delta, 16);
    r.z = __shfl_up_sync(0xffffffffu, v.z, delta, 16);
    r.w = __shfl_up_sync(0xffffffffu, v.w, delta, 16);
    return r;
}

__global__ __launch_bounds__(NTHREADS, 2)
void pose_scan_kernel(const float4* __restrict__ q,
                      const float4* __restrict__ noise,
                      float4* __restrict__ out)
{
    __shared__ float4 s_agg [SLOTS][COLS + 1];  // per-slot inclusive chunk product (+1: bank pad)
    __shared__ float4 s_excl[SLOTS][COLS + 1];  // per-slot exclusive prefix (incl. carry)
    __shared__ float4 s_carry[COLS];            // running state across tiles

    const int tx   = threadIdx.x;
    const int col  = tx & (COLS - 1);
    const int slot = tx / COLS;
    const int n    = blockIdx.x * COLS + col;

    // scan-phase mapping: warp w handles cols {2w, 2w+1}; lanes 0-15 = slots of col 2w,
    // lanes 16-31 = slots of col 2w+1.
    const int lane  = tx & 31;
    const int sl    = lane & 15;                   // slot index within segment
    const int scol  = 2 * (tx >> 5) + (lane >> 4); // column this lane scans

    // Seed carry with q[0]; emit output row 0.
    if (slot == 0) {
        float4 q0 = q[n];
        s_carry[col] = q0;
        out[n] = q0;
    }

    float4 qb[CSTEP + 1];
    float4 nb[CSTEP];

    // Prime loads for tile 0.
    {
        const int t0 = slot * CSTEP;
        #pragma unroll
        for (int i = 0; i <= CSTEP; i++) qb[i] = q[min(t0 + i, TS - 1) * NS + n];
        #pragma unroll
        for (int i = 0; i < CSTEP; i++)  nb[i] = noise[min(t0 + i, STEPS - 1) * NS + n];
    }

    float4 L[CSTEP];   // local inclusive chain (newest factor on the left)

    for (int tile = 0; tile < NTILES; tile++) {
        const int t0 = tile * TILE + slot * CSTEP;

        // ---- phase 1: local chain over CSTEP steps (registers only) ----
        float4 acc = make_float4(1.f, 0.f, 0.f, 0.f);
        #pragma unroll
        for (int i = 0; i < CSTEP; i++) {
            float4 qd = qmul_conj4(qb[i + 1], qb[i]);          // q[t+1] * conj(q[t])
            float vw =  nb[i].x - 0.5f;
            float vx = (nb[i].y - 0.5f) * 0.05f;
            float vy = (nb[i].z - 0.5f) * 0.05f;
            float vz = (nb[i].w - 0.5f) * 0.05f;
            float rn = rsqrtf(vw*vw + vx*vx + vy*vy + vz*vz);
            float4 qs = make_float4(vw*rn, vx*rn, vy*rn, vz*rn);
            float4 qd2 = qmul4(qd, qs);
            if (t0 + i >= STEPS) qd2 = make_float4(1.f, 0.f, 0.f, 0.f);  // pad identity
            acc = (i == 0) ? qd2 : qmul4(qd2, acc);
            L[i] = acc;
        }
        s_agg[slot][col] = acc;

        // ---- prefetch next tile BEFORE the sync so LDGs fly under the scan ----
        if (tile + 1 < NTILES) {
            const int t1 = (tile + 1) * TILE + slot * CSTEP;
            #pragma unroll
            for (int i = 0; i <= CSTEP; i++) qb[i] = q[min(t1 + i, TS - 1) * NS + n];
            #pragma unroll
            for (int i = 0; i < CSTEP; i++)  nb[i] = noise[min(t1 + i, STEPS - 1) * NS + n];
        }

        __syncthreads();

        // ---- phase 2: Kogge-Stone shuffle scan across slots (all warps) ----
        {
            float4 v = s_agg[sl][scol];            // inclusive scan value for (scol, sl)
            #pragma unroll
            for (int off = 1; off < SLOTS; off <<= 1) {
                float4 u = shfl_up4(v, off);
                if (sl >= off) v = qmul4(v, u);    // newer(v) * older(u)
            }
            // v is now I[sl] = agg[sl] * ... * agg[0]
            float4 Iprev = shfl_up4(v, 1);         // I[sl-1]; garbage at sl==0
            float4 carry = s_carry[scol];
            float4 E = (sl == 0) ? carry : qmul4(Iprev, carry);
            s_excl[sl][scol] = E;
            if (sl == SLOTS - 1) s_carry[scol] = qmul4(v, carry);
        }
        __syncthreads();

        // ---- phase 3: apply exclusive prefix, write outputs (coalesced STG.128) ----
        float4 E = s_excl[slot][col];
        #pragma unroll
        for (int i = 0; i < CSTEP; i++) {
            int t = t0 + i;
            if (t < STEPS) out[(t + 1) * NS + n] = qmul4(L[i], E);
        }
    }
}

extern "C" void kernel_launch(void* const* d_in, const int* in_sizes, int n_in,
                              void* d_out, int out_size)
{
    const float4* q     = (const float4*)d_in[0];   // [2048, 4096, 4] f32
    const float4* noise = (const float4*)d_in[1];   // [2047, 4096, 4] f32
    float4* out         = (float4*)d_out;           // [2048, 4096, 4] f32

    pose_scan_kernel<<<NS / COLS, NTHREADS>>>(q, noise, out);
}